// round 13
// baseline (speedup 1.0000x reference)
#include <cuda_runtime.h>
#include <cuda_fp16.h>
#include <math.h>
#include <stdint.h>

#define SEQ   1024
#define DM    2048
#define NH    32
#define HD    64
#define NBLK  16
#define DFFN  8192
#define NE    4
#define CAP   1024
#define VOCAB 50257

// ---------------- scratch (device globals; no allocation) ----------------
static __device__ float  g_x   [SEQ*DM];
static __device__ __half g_xh  [SEQ*DM];
static __device__ float  g_q   [SEQ*DM];
static __device__ float  g_k   [SEQ*DM];
static __device__ float  g_v   [SEQ*DM];
static __device__ float  g_attnf[SEQ*DM];
static __device__ float  g_L   [SEQ*NH];
static __device__ __half g_attnh[SEQ*DM];
static __device__ float  g_xres[SEQ*DM];
static __device__ float  g_xln [SEQ*DM];
static __device__ __half g_xlnh[SEQ*DM];
static __device__ __half g_xfinh[SEQ*DM];
static __device__ float  g_moe [SEQ*DM];
static __device__ float  g_glog[SEQ*NE];
static __device__ int    g_cnt [NE];
static __device__ int    g_idx [NE*CAP];
static __device__ float  g_wt  [NE*CAP];
static __device__ __half g_h1  [(size_t)NE*CAP*DFFN];
static __device__ __half g_h3  [(size_t)NE*CAP*DFFN];
// fp16 weight copies
static __device__ __half g_wqh [DM*DM];
static __device__ __half g_wkh [DM*DM];
static __device__ __half g_wvh [DM*DM];
static __device__ __half g_woh [DM*DM];
static __device__ __half g_w1h [(size_t)NE*DFFN*DM];
static __device__ __half g_w2h [(size_t)NE*DM*DFFN];
static __device__ __half g_w3h [(size_t)NE*DFFN*DM];
static __device__ __half g_hwh [(size_t)VOCAB*DM];

// ---------------- helpers ----------------
__device__ __forceinline__ void ldsm4(uint32_t r[4], uint32_t addr){
    asm volatile("ldmatrix.sync.aligned.m8n8.x4.shared.b16 {%0,%1,%2,%3}, [%4];"
        : "=r"(r[0]), "=r"(r[1]), "=r"(r[2]), "=r"(r[3]) : "r"(addr));
}
__device__ __forceinline__ void mma_fp16(float c[4], const uint32_t a[4], const uint32_t b[2]){
    asm volatile("mma.sync.aligned.m16n8k16.row.col.f32.f16.f16.f32 "
        "{%0,%1,%2,%3},{%4,%5,%6,%7},{%8,%9},{%0,%1,%2,%3};"
        : "+f"(c[0]), "+f"(c[1]), "+f"(c[2]), "+f"(c[3])
        : "r"(a[0]), "r"(a[1]), "r"(a[2]), "r"(a[3]), "r"(b[0]), "r"(b[1]));
}
__device__ __forceinline__ void cpa16(__half* dst, const __half* src, int bytes){
    uint32_t d = (uint32_t)__cvta_generic_to_shared(dst);
    asm volatile("cp.async.cg.shared.global [%0], [%1], 16, %2;" :: "r"(d), "l"(src), "r"(bytes));
}
__device__ __forceinline__ void cpa_commit(){ asm volatile("cp.async.commit_group;"); }
__device__ __forceinline__ void cpa_wait0(){ asm volatile("cp.async.wait_group 0;"); }

// ---------------- fp32 -> fp16 conversion (streaming) ----------------
__global__ void k_f2h(const float* __restrict__ s, __half* __restrict__ d, int n8)
{
    int i = blockIdx.x * blockDim.x + threadIdx.x;
    if (i >= n8) return;
    const float4* s4 = (const float4*)s;
    float4 a = __ldcs(s4 + 2*i), b = __ldcs(s4 + 2*i + 1);
    __half2 h0 = __floats2half2_rn(a.x, a.y), h1 = __floats2half2_rn(a.z, a.w);
    __half2 h2 = __floats2half2_rn(b.x, b.y), h3 = __floats2half2_rn(b.z, b.w);
    uint4 o;
    o.x = *(uint32_t*)&h0; o.y = *(uint32_t*)&h1;
    o.z = *(uint32_t*)&h2; o.w = *(uint32_t*)&h3;
    __stcs(((uint4*)d) + i, o);
}

// ---------------- FP16 GEMM 128x128 (qkv / wo), 2-stage cp.async ----------------
template<int RESID>
__global__ void __launch_bounds__(256) k_mm(
    const __half* __restrict__ A, const __half* __restrict__ Bw,
    float* __restrict__ Cf, int M, int N, int K, int ldc,
    const float* __restrict__ resid)
{
    extern __shared__ __half sm[];
    const int tid = threadIdx.x;
    const int mb = blockIdx.y * 128;
    const int nb = blockIdx.x * 128;

    const __half* apt[4]; const __half* bpt[4]; int trow[4]; int tseg[4];
    #pragma unroll
    for (int i = 0; i < 4; i++) {
        int task = tid + 256*i;
        int row = task >> 3, seg = task & 7;
        trow[i] = row; tseg[i] = seg;
        apt[i] = A + (size_t)(mb + row) * K + seg*8;
        bpt[i] = Bw + (size_t)(nb + row) * K + seg*8;
    }

    auto load_tile = [&](int kt, int buf){
        int k0 = kt * 64;
        __half* base = sm + buf * 16384;
        #pragma unroll
        for (int i = 0; i < 4; i++) {
            int off = trow[i]*64 + ((tseg[i] ^ (trow[i] & 7)) << 3);
            cpa16(base + off,        apt[i] + k0, 16);
            cpa16(base + 8192 + off, bpt[i] + k0, 16);
        }
        cpa_commit();
    };

    const int warp = tid >> 5, lane = tid & 31;
    const int gid = lane >> 2, tig = lane & 3;
    const int lrow = lane & 15, lch = lane >> 4;
    const int wm = (warp & 1) * 64;
    const int wn = (warp >> 1) * 32;
    float acc[4][4][4];
    #pragma unroll
    for (int a = 0; a < 4; a++)
    #pragma unroll
    for (int b = 0; b < 4; b++)
    #pragma unroll
    for (int c = 0; c < 4; c++) acc[a][b][c] = 0.f;

    const uint32_t smbase = (uint32_t)__cvta_generic_to_shared(sm);
    const int nkt = K / 64;
    load_tile(0, 0);
    int p = 0;
    for (int kt = 0; kt < nkt; kt++) {
        cpa_wait0();
        __syncthreads();
        if (kt + 1 < nkt) load_tile(kt + 1, p ^ 1);
        uint32_t abase = smbase + p * 32768;
        uint32_t bbase = abase + 16384;
        #pragma unroll
        for (int ks = 0; ks < 4; ks++) {
            int c0 = ks * 2;
            uint32_t af[4][4];
            #pragma unroll
            for (int mt = 0; mt < 4; mt++) {
                int row = wm + mt*16 + lrow;
                int ch = (c0 + lch) ^ (row & 7);
                ldsm4(af[mt], abase + (row*64 + ch*8)*2);
            }
            uint32_t bfr[2][4];
            #pragma unroll
            for (int bg = 0; bg < 2; bg++) {
                int row = wn + bg*16 + lrow;
                int ch = (c0 + lch) ^ (row & 7);
                ldsm4(bfr[bg], bbase + (row*64 + ch*8)*2);
            }
            #pragma unroll
            for (int mt = 0; mt < 4; mt++)
            #pragma unroll
            for (int nt = 0; nt < 4; nt++) {
                uint32_t bb[2] = { bfr[nt>>1][nt&1], bfr[nt>>1][(nt&1)+2] };
                mma_fp16(acc[mt][nt], af[mt], bb);
            }
        }
        p ^= 1;
    }

    #pragma unroll
    for (int mt = 0; mt < 4; mt++) {
        #pragma unroll
        for (int nt = 0; nt < 4; nt++) {
            int n = nb + wn + nt*8 + tig*2;
            #pragma unroll
            for (int half = 0; half < 2; half++) {
                int m = mb + wm + mt*16 + gid + half*8;
                float v0 = acc[mt][nt][half*2 + 0];
                float v1 = acc[mt][nt][half*2 + 1];
                float r0 = RESID ? resid[(size_t)m*ldc + n] : 0.f;
                float r1 = RESID ? resid[(size_t)m*ldc + n + 1] : 0.f;
                Cf[(size_t)m*ldc + n]     = v0 + r0;
                Cf[(size_t)m*ldc + n + 1] = v1 + r1;
            }
        }
    }
}

// ---------------- FP16 GEMM 128x256, 64x64 warp tiles (MoE up/down, head) ----------------
// MODE 0: plain fp32 C with N guards (head)
// MODE 2: MoE gather -> fp16 H buffer (per expert), N = DFFN
// MODE 3: MoE down scatter atomic -> g_moe, N = DM
template<int MODE>
__global__ void __launch_bounds__(256) k_mm2(
    const __half* __restrict__ A, const __half* __restrict__ Bw,
    void* __restrict__ Cv, int M, int N, int K, int ldc)
{
    extern __shared__ __half sm2[];   // 2 stages x (A 8192 + B 16384) halves = 96KB
    const int tid = threadIdx.x;
    const int mb = blockIdx.y * 128;
    const int nb = blockIdx.x * 256;
    int cnt = M;
    const int* ridx = nullptr;
    const float* wts = nullptr;
    float* Cf = (float*)Cv;
    __half* Ch = (__half*)Cv;
    if (MODE == 2 || MODE == 3) {
        int e = blockIdx.z;
        cnt = g_cnt[e];
        if (mb >= cnt) return;
        ridx = g_idx + e*CAP;
        wts  = g_wt  + e*CAP;
        Bw += (size_t)e * (size_t)N * K;
        if (MODE == 2) Ch += (size_t)e * CAP * N;
        if (MODE == 3) A  += (size_t)e * CAP * K;
    }

    // A: 1024 tasks (128 rows x 8 segs), 4/thread. B: 2048 tasks (256 rows x 8 segs), 8/thread.
    const __half* apt[4]; int atr[4]; int ats[4];
    const __half* bpt[8]; int btr[8]; int bts[8];
    #pragma unroll
    for (int i = 0; i < 4; i++) {
        int task = tid + 256*i;
        int row = task >> 3, seg = task & 7;
        atr[i] = row; ats[i] = seg;
        int am = mb + row;
        int arow;
        if (MODE == 2)      arow = (am < cnt) ? ridx[am] : 0;
        else if (MODE == 3) arow = (am < cnt) ? am : 0;
        else                arow = am;
        apt[i] = A + (size_t)arow * K + seg*8;
    }
    #pragma unroll
    for (int i = 0; i < 8; i++) {
        int task = tid + 256*i;
        int row = task >> 3, seg = task & 7;
        btr[i] = row; bts[i] = seg;
        int bn = nb + row;
        int bnc = (bn < N) ? bn : (N - 1);
        bpt[i] = Bw + (size_t)bnc * K + seg*8;
    }

    auto load_tile = [&](int kt, int buf){
        int k0 = kt * 64;
        __half* base = sm2 + buf * 24576;
        #pragma unroll
        for (int i = 0; i < 4; i++) {
            int off = atr[i]*64 + ((ats[i] ^ (atr[i] & 7)) << 3);
            cpa16(base + off, apt[i] + k0, 16);
        }
        __half* bb = base + 8192;
        #pragma unroll
        for (int i = 0; i < 8; i++) {
            int off = btr[i]*64 + ((bts[i] ^ (btr[i] & 7)) << 3);
            cpa16(bb + off, bpt[i] + k0, 16);
        }
        cpa_commit();
    };

    const int warp = tid >> 5, lane = tid & 31;
    const int gid = lane >> 2, tig = lane & 3;
    const int lrow = lane & 15, lch = lane >> 4;
    const int wm = (warp & 1) * 64;
    const int wn = (warp >> 1) * 64;
    float acc[4][8][4];
    #pragma unroll
    for (int a = 0; a < 4; a++)
    #pragma unroll
    for (int b = 0; b < 8; b++)
    #pragma unroll
    for (int c = 0; c < 4; c++) acc[a][b][c] = 0.f;

    const uint32_t smbase = (uint32_t)__cvta_generic_to_shared(sm2);
    const int nkt = K / 64;
    load_tile(0, 0);
    int p = 0;
    for (int kt = 0; kt < nkt; kt++) {
        cpa_wait0();
        __syncthreads();
        if (kt + 1 < nkt) load_tile(kt + 1, p ^ 1);
        uint32_t abase = smbase + p * 49152;
        uint32_t bbase = abase + 16384;
        #pragma unroll
        for (int ks = 0; ks < 4; ks++) {
            int c0 = ks * 2;
            uint32_t af[4][4];
            #pragma unroll
            for (int mt = 0; mt < 4; mt++) {
                int row = wm + mt*16 + lrow;
                int ch = (c0 + lch) ^ (row & 7);
                ldsm4(af[mt], abase + (row*64 + ch*8)*2);
            }
            uint32_t bfr[4][4];
            #pragma unroll
            for (int bg = 0; bg < 4; bg++) {
                int row = wn + bg*16 + lrow;
                int ch = (c0 + lch) ^ (row & 7);
                ldsm4(bfr[bg], bbase + (row*64 + ch*8)*2);
            }
            #pragma unroll
            for (int mt = 0; mt < 4; mt++)
            #pragma unroll
            for (int nt = 0; nt < 8; nt++) {
                uint32_t bb[2] = { bfr[nt>>1][nt&1], bfr[nt>>1][(nt&1)+2] };
                mma_fp16(acc[mt][nt], af[mt], bb);
            }
        }
        p ^= 1;
    }

    // epilogue
    #pragma unroll
    for (int mt = 0; mt < 4; mt++) {
        #pragma unroll
        for (int nt = 0; nt < 8; nt++) {
            int n = nb + wn + nt*8 + tig*2;
            #pragma unroll
            for (int half = 0; half < 2; half++) {
                int m = mb + wm + mt*16 + gid + half*8;
                float v0 = acc[mt][nt][half*2 + 0];
                float v1 = acc[mt][nt][half*2 + 1];
                if (MODE == 2) {
                    if (m < cnt) {
                        *(__half2*)&Ch[(size_t)m*N + n] = __floats2half2_rn(v0, v1);
                    }
                } else if (MODE == 3) {
                    if (m < cnt) {
                        int tok = ridx[m]; float w = wts[m];
                        atomicAdd(&g_moe[(size_t)tok*DM + n],     w * v0);
                        atomicAdd(&g_moe[(size_t)tok*DM + n + 1], w * v1);
                    }
                } else {
                    if (n < N)     Cf[(size_t)m*ldc + n]     = v0;
                    if (n + 1 < N) Cf[(size_t)m*ldc + n + 1] = v1;
                }
            }
        }
    }
}

// ---------------- embedding (fp32 + fp16 copies) ----------------
__global__ void k_embed(const int* __restrict__ tok, const float* __restrict__ emb)
{
    int i = blockIdx.x * blockDim.x + threadIdx.x;
    int t = i >> 11;
    int c = i & 2047;
    float v = emb[(size_t)tok[t]*DM + c];
    g_x[i]  = v;
    g_xh[i] = __float2half_rn(v);
}

// ---------------- h1 = silu(h1) * h3 ----------------
__global__ void k_silumul()
{
    size_t i = (size_t)blockIdx.x * blockDim.x + threadIdx.x;
    __half2 a2 = ((const __half2*)g_h1)[i];
    __half2 b2 = ((const __half2*)g_h3)[i];
    float2 a = __half22float2(a2);
    float2 b = __half22float2(b2);
    float r0 = a.x / (1.f + expf(-a.x)) * b.x;
    float r1 = a.y / (1.f + expf(-a.y)) * b.y;
    ((__half2*)g_h1)[i] = __floats2half2_rn(r0, r1);
}

// ---------------- RoPE ----------------
__global__ void k_rope()
{
    int i = blockIdx.x * blockDim.x + threadIdx.x;
    if (i >= SEQ*DM/2) return;
    int t  = i / (DM/2);
    int cp = i % (DM/2);
    int hp = cp & 31;
    float ex  = -(float)hp * 0.41524101186524409f;
    float inv = exp2f(ex);
    float ang = (float)t * inv;
    float s, c;
    sincosf(ang, &s, &c);
    int base = t*DM + 2*cp;
    float q0 = g_q[base], q1 = g_q[base+1];
    g_q[base]   = q0*c - q1*s;
    g_q[base+1] = q0*s + q1*c;
    float k0 = g_k[base], k1 = g_k[base+1];
    g_k[base]   = k0*c - k1*s;
    g_k[base+1] = k0*s + k1*c;
}

// ---------------- block attention, split over jb parity, atomic accumulate ----------------
#define AST 68
__global__ void __launch_bounds__(256) k_attn3()
{
    extern __shared__ float smf[];
    float* Qs = smf;
    float* Ks = Qs + 64*AST;
    float* Vt = Ks + 64*AST;
    float* Ps = Vt + 64*AST;
    const int h  = blockIdx.x;
    const int ib = (NBLK - 1) - blockIdx.y;
    const int z  = blockIdx.z;
    if (z > ib) return;
    const int tid = threadIdx.x;
    const int rq = (tid >> 4) * 4;
    const int cq = tid & 15;

    {
        int r = tid >> 2, dg = (tid & 3) * 16;
        const float* src = g_q + (size_t)(ib*64 + r)*DM + h*64 + dg;
        float* dst = Qs + r*AST + dg;
        #pragma unroll
        for (int q = 0; q < 4; q++) ((float4*)dst)[q] = ((const float4*)src)[q];
    }

    float acc_o[4][4];
    #pragma unroll
    for (int i = 0; i < 4; i++)
    #pragma unroll
    for (int j = 0; j < 4; j++) acc_o[i][j] = 0.f;
    float lsum[4] = {0.f, 0.f, 0.f, 0.f};

    for (int jb = z; jb <= ib; jb += 2) {
        __syncthreads();
        {
            int r = tid >> 2, dg = (tid & 3) * 16;
            const float* ksrc = g_k + (size_t)(jb*64 + r)*DM + h*64 + dg;
            const float* vsrc = g_v + (size_t)(jb*64 + r)*DM + h*64 + dg;
            float* kd = Ks + r*AST + dg;
            #pragma unroll
            for (int q = 0; q < 4; q++) ((float4*)kd)[q] = ((const float4*)ksrc)[q];
            #pragma unroll
            for (int q = 0; q < 4; q++) {
                float4 v = ((const float4*)vsrc)[q];
                int d0 = dg + 4*q;
                Vt[(d0+0)*AST + r] = v.x;
                Vt[(d0+1)*AST + r] = v.y;
                Vt[(d0+2)*AST + r] = v.z;
                Vt[(d0+3)*AST + r] = v.w;
            }
        }
        __syncthreads();

        float s[4][4];
        #pragma unroll
        for (int i = 0; i < 4; i++)
        #pragma unroll
        for (int j = 0; j < 4; j++) s[i][j] = 0.f;
        for (int d0 = 0; d0 < 64; d0 += 4) {
            float4 q4[4], k4[4];
            #pragma unroll
            for (int i = 0; i < 4; i++) q4[i] = *(const float4*)(Qs + (rq+i)*AST + d0);
            #pragma unroll
            for (int j = 0; j < 4; j++) k4[j] = *(const float4*)(Ks + (cq+16*j)*AST + d0);
            #pragma unroll
            for (int i = 0; i < 4; i++)
            #pragma unroll
            for (int j = 0; j < 4; j++)
                s[i][j] += q4[i].x*k4[j].x + q4[i].y*k4[j].y + q4[i].z*k4[j].z + q4[i].w*k4[j].w;
        }
        #pragma unroll
        for (int i = 0; i < 4; i++)
        #pragma unroll
        for (int j = 0; j < 4; j++) {
            s[i][j] *= 0.125f;
            if (jb == ib && (cq + 16*j) > (rq + i)) s[i][j] = -INFINITY;
        }
        float mx[4];
        #pragma unroll
        for (int i = 0; i < 4; i++) {
            float m = s[i][0];
            #pragma unroll
            for (int j = 1; j < 4; j++) m = fmaxf(m, s[i][j]);
            #pragma unroll
            for (int o = 1; o < 16; o <<= 1) m = fmaxf(m, __shfl_xor_sync(0xffffffffu, m, o));
            mx[i] = m;
        }
        #pragma unroll
        for (int i = 0; i < 4; i++)
        #pragma unroll
        for (int j = 0; j < 4; j++) {
            float pv = expf(s[i][j] - mx[i]);
            lsum[i] += pv;
            Ps[(rq+i)*AST + cq + 16*j] = pv;
        }
        __syncthreads();

        for (int c0 = 0; c0 < 64; c0 += 4) {
            float4 p4[4], v4[4];
            #pragma unroll
            for (int i = 0; i < 4; i++) p4[i] = *(const float4*)(Ps + (rq+i)*AST + c0);
            #pragma unroll
            for (int j = 0; j < 4; j++) v4[j] = *(const float4*)(Vt + (cq+16*j)*AST + c0);
            #pragma unroll
            for (int i = 0; i < 4; i++)
            #pragma unroll
            for (int j = 0; j < 4; j++)
                acc_o[i][j] += p4[i].x*v4[j].x + p4[i].y*v4[j].y + p4[i].z*v4[j].z + p4[i].w*v4[j].w;
        }
    }

    #pragma unroll
    for (int i = 0; i < 4; i++) {
        float l = lsum[i];
        #pragma unroll
        for (int o = 1; o < 16; o <<= 1) l += __shfl_xor_sync(0xffffffffu, l, o);
        if (cq == 0) atomicAdd(&g_L[(ib*64 + rq + i)*NH + h], l);
        #pragma unroll
        for (int j = 0; j < 4; j++)
            atomicAdd(&g_attnf[(size_t)(ib*64 + rq + i)*DM + h*64 + cq + 16*j], acc_o[i][j]);
    }
}

// ---------------- attention normalize ----------------
__global__ void k_attn_norm()
{
    int i = blockIdx.x * blockDim.x + threadIdx.x;
    int t = i >> 11;
    int c = i & 2047;
    int h = c >> 6;
    float l = g_L[t*NH + h];
    g_attnh[i] = __float2half_rn(g_attnf[i] / (l + 1e-6f));
}

// ---------------- layernorm (fp32 + fp16 out) ----------------
__global__ void k_ln(const float* __restrict__ in, const float* __restrict__ g,
                     const float* __restrict__ b, float* __restrict__ out,
                     __half* __restrict__ outh)
{
    __shared__ float red[256];
    const int row = blockIdx.x, tid = threadIdx.x;
    const float* x = in + (size_t)row*DM;
    float s = 0.f;
    for (int c = tid; c < DM; c += 256) s += x[c];
    red[tid] = s; __syncthreads();
    for (int o = 128; o > 0; o >>= 1) { if (tid < o) red[tid] += red[tid+o]; __syncthreads(); }
    float mu = red[0] * (1.f/DM);
    __syncthreads();
    float vs = 0.f;
    for (int c = tid; c < DM; c += 256) { float d = x[c]-mu; vs += d*d; }
    red[tid] = vs; __syncthreads();
    for (int o = 128; o > 0; o >>= 1) { if (tid < o) red[tid] += red[tid+o]; __syncthreads(); }
    float rstd = rsqrtf(red[0]*(1.f/DM) + 1e-5f);
    for (int c = tid; c < DM; c += 256) {
        float v = (x[c]-mu)*rstd*g[c] + b[c];
        out[(size_t)row*DM + c] = v;
        outh[(size_t)row*DM + c] = __float2half_rn(v);
    }
}

// ---------------- fused: v = moe + xln; LN(ln2); LN(fin) -> g_xfinh ----------------
__global__ void k_lnln(const float* __restrict__ g2, const float* __restrict__ b2,
                       const float* __restrict__ gf, const float* __restrict__ bf)
{
    __shared__ float buf[DM];
    __shared__ float red[256];
    const int row = blockIdx.x, tid = threadIdx.x;
    float s = 0.f;
    for (int c = tid; c < DM; c += 256) {
        float v = g_moe[(size_t)row*DM + c] + g_xln[(size_t)row*DM + c];
        buf[c] = v; s += v;
    }
    red[tid] = s; __syncthreads();
    for (int o = 128; o > 0; o >>= 1) { if (tid < o) red[tid] += red[tid+o]; __syncthreads(); }
    float mu = red[0] * (1.f/DM);
    __syncthreads();
    float vs = 0.f;
    for (int c = tid; c < DM; c += 256) { float d = buf[c]-mu; vs += d*d; }
    red[tid] = vs; __syncthreads();
    for (int o = 128; o > 0; o >>= 1) { if (tid < o) red[tid] += red[tid+o]; __syncthreads(); }
    float rstd = rsqrtf(red[0]*(1.f/DM) + 1e-5f);
    __syncthreads();
    for (int c = tid; c < DM; c += 256)
        buf[c] = (buf[c]-mu)*rstd*g2[c] + b2[c];
    __syncthreads();
    s = 0.f;
    for (int c = tid; c < DM; c += 256) s += buf[c];
    red[tid] = s; __syncthreads();
    for (int o = 128; o > 0; o >>= 1) { if (tid < o) red[tid] += red[tid+o]; __syncthreads(); }
    mu = red[0] * (1.f/DM);
    __syncthreads();
    vs = 0.f;
    for (int c = tid; c < DM; c += 256) { float d = buf[c]-mu; vs += d*d; }
    red[tid] = vs; __syncthreads();
    for (int o = 128; o > 0; o >>= 1) { if (tid < o) red[tid] += red[tid+o]; __syncthreads(); }
    rstd = rsqrtf(red[0]*(1.f/DM) + 1e-5f);
    __syncthreads();
    for (int c = tid; c < DM; c += 256)
        g_xfinh[(size_t)row*DM + c] = __float2half_rn((buf[c]-mu)*rstd*gf[c] + bf[c]);
}

// ---------------- gate logits ----------------
__global__ void k_gate(const float* __restrict__ gw)
{
    __shared__ float red[NE*128];
    const int t = blockIdx.x, tid = threadIdx.x;
    float p0=0.f,p1=0.f,p2=0.f,p3=0.f;
    const float* x = g_xln + (size_t)t*DM;
    for (int c = tid; c < DM; c += 128) {
        float xv = x[c];
        p0 += xv * gw[c];
        p1 += xv * gw[DM + c];
        p2 += xv * gw[2*DM + c];
        p3 += xv * gw[3*DM + c];
    }
    red[0*128+tid]=p0; red[1*128+tid]=p1; red[2*128+tid]=p2; red[3*128+tid]=p3;
    __syncthreads();
    for (int o = 64; o > 0; o >>= 1) {
        if (tid < o) {
#pragma unroll
            for (int e = 0; e < NE; e++) red[e*128+tid] += red[e*128+tid+o];
        }
        __syncthreads();
    }
    if (tid < NE) g_glog[t*NE + tid] = red[tid*128];
}

// ---------------- aux ----------------
__global__ void k_aux(float* __restrict__ out, int out_size)
{
    __shared__ float red[1024];
    const int t = threadIdx.x;
    float l0 = g_glog[t*4+0], l1 = g_glog[t*4+1], l2 = g_glog[t*4+2], l3 = g_glog[t*4+3];
    float mu = (l0+l1+l2+l3) * 0.25f;
    float v = ((l0-mu)*(l0-mu) + (l1-mu)*(l1-mu) + (l2-mu)*(l2-mu) + (l3-mu)*(l3-mu)) / 3.f;
    red[t] = v; __syncthreads();
    for (int o = 512; o > 0; o >>= 1) { if (t < o) red[t] += red[t+o]; __syncthreads(); }
    if (t == 0) out[out_size - 1] = red[0] * (1.f/SEQ);
}

// ---------------- zero accumulators + counters ----------------
__global__ void k_zero()
{
    int i = blockIdx.x * blockDim.x + threadIdx.x;
    if (i < SEQ*DM) { g_moe[i] = 0.f; g_attnf[i] = 0.f; }
    if (i < SEQ*NH) g_L[i] = 0.f;
    if (i < NE) g_cnt[i] = 0;
}

// ---------------- routing ----------------
__global__ void k_route()
{
    int t = blockIdx.x * blockDim.x + threadIdx.x;
    if (t >= SEQ) return;
    float l[NE];
#pragma unroll
    for (int e = 0; e < NE; e++) l[e] = g_glog[t*NE + e];
    float m = l[0];
#pragma unroll
    for (int e = 1; e < NE; e++) m = fmaxf(m, l[e]);
    float ex[NE], sum = 0.f;
#pragma unroll
    for (int e = 0; e < NE; e++) { ex[e] = expf(l[e]-m); sum += ex[e]; }
    float p[NE];
#pragma unroll
    for (int e = 0; e < NE; e++) p[e] = ex[e]/sum;
    int i0 = 0;
#pragma unroll
    for (int e = 1; e < NE; e++) if (p[e] > p[i0]) i0 = e;
    int i1 = -1;
#pragma unroll
    for (int e = 0; e < NE; e++) if (e != i0 && (i1 < 0 || p[e] > p[i1])) i1 = e;
    float w0 = p[i0], w1 = p[i1];
    float ws = w0 + w1; w0 /= ws; w1 /= ws;
    int s0 = atomicAdd(&g_cnt[i0], 1);
    g_idx[i0*CAP + s0] = t; g_wt[i0*CAP + s0] = w0;
    int s1 = atomicAdd(&g_cnt[i1], 1);
    g_idx[i1*CAP + s1] = t; g_wt[i1*CAP + s1] = w1;
}

// ---------------- launch ----------------
extern "C" void kernel_launch(void* const* d_in, const int* in_sizes, int n_in,
                              void* d_out, int out_size)
{
    const int*   tokens = (const int*)  d_in[0];
    const float* emb    = (const float*)d_in[1];
    const float* wq     = (const float*)d_in[2];
    const float* wk     = (const float*)d_in[3];
    const float* wv     = (const float*)d_in[4];
    const float* wo     = (const float*)d_in[5];
    const float* ln1g   = (const float*)d_in[6];
    const float* ln1b   = (const float*)d_in[7];
    const float* gatew  = (const float*)d_in[8];
    const float* w1     = (const float*)d_in[9];
    const float* w2     = (const float*)d_in[10];
    const float* w3     = (const float*)d_in[11];
    const float* ln2g   = (const float*)d_in[12];
    const float* ln2b   = (const float*)d_in[13];
    const float* fing   = (const float*)d_in[14];
    const float* finb   = (const float*)d_in[15];
    const float* headw  = (const float*)d_in[16];
    float* out = (float*)d_out;

    float *p_x, *p_q, *p_k, *p_v, *p_xres, *p_xln;
    __half *p_xh, *p_attnh, *p_xlnh, *p_xfinh, *p_h1, *p_h3;
    __half *p_wqh, *p_wkh, *p_wvh, *p_woh, *p_w1h, *p_w2h, *p_w3h, *p_hwh;
    cudaGetSymbolAddress((void**)&p_x,     g_x);
    cudaGetSymbolAddress((void**)&p_q,     g_q);
    cudaGetSymbolAddress((void**)&p_k,     g_k);
    cudaGetSymbolAddress((void**)&p_v,     g_v);
    cudaGetSymbolAddress((void**)&p_xres,  g_xres);
    cudaGetSymbolAddress((void**)&p_xln,   g_xln);
    cudaGetSymbolAddress((void**)&p_xh,    g_xh);
    cudaGetSymbolAddress((void**)&p_attnh, g_attnh);
    cudaGetSymbolAddress((void**)&p_xlnh,  g_xlnh);
    cudaGetSymbolAddress((void**)&p_xfinh, g_xfinh);
    cudaGetSymbolAddress((void**)&p_h1,    g_h1);
    cudaGetSymbolAddress((void**)&p_h3,    g_h3);
    cudaGetSymbolAddress((void**)&p_wqh,   g_wqh);
    cudaGetSymbolAddress((void**)&p_wkh,   g_wkh);
    cudaGetSymbolAddress((void**)&p_wvh,   g_wvh);
    cudaGetSymbolAddress((void**)&p_woh,   g_woh);
    cudaGetSymbolAddress((void**)&p_w1h,   g_w1h);
    cudaGetSymbolAddress((void**)&p_w2h,   g_w2h);
    cudaGetSymbolAddress((void**)&p_w3h,   g_w3h);
    cudaGetSymbolAddress((void**)&p_hwh,   g_hwh);

    static int attr_done = 0;
    if (!attr_done) {
        cudaFuncSetAttribute(k_mm<0>,  cudaFuncAttributeMaxDynamicSharedMemorySize, 65536);
        cudaFuncSetAttribute(k_mm<1>,  cudaFuncAttributeMaxDynamicSharedMemorySize, 65536);
        cudaFuncSetAttribute(k_mm2<0>, cudaFuncAttributeMaxDynamicSharedMemorySize, 98304);
        cudaFuncSetAttribute(k_mm2<2>, cudaFuncAttributeMaxDynamicSharedMemorySize, 98304);
        cudaFuncSetAttribute(k_mm2<3>, cudaFuncAttributeMaxDynamicSharedMemorySize, 98304);
        cudaFuncSetAttribute(k_attn3,  cudaFuncAttributeMaxDynamicSharedMemorySize, 4*64*AST*4);
        attr_done = 1;
    }

    k_zero<<<SEQ*DM/256, 256>>>();

    // ---- weight conversions (fp32 -> fp16) ----
    {
        int n8 = DM*DM/8;
        k_f2h<<<(n8+255)/256, 256>>>(wq, p_wqh, n8);
        k_f2h<<<(n8+255)/256, 256>>>(wk, p_wkh, n8);
        k_f2h<<<(n8+255)/256, 256>>>(wv, p_wvh, n8);
        k_f2h<<<(n8+255)/256, 256>>>(wo, p_woh, n8);
        int nf = (int)((size_t)NE*DFFN*DM/8);
        k_f2h<<<(nf+255)/256, 256>>>(w1, p_w1h, nf);
        k_f2h<<<(nf+255)/256, 256>>>(w2, p_w2h, nf);
        k_f2h<<<(nf+255)/256, 256>>>(w3, p_w3h, nf);
        int nh = (int)((size_t)VOCAB*DM/8);
        k_f2h<<<(nh+255)/256, 256>>>(headw, p_hwh, nh);
    }

    k_embed<<<SEQ*DM/256, 256>>>(tokens, emb);

    dim3 gproj(DM/128, SEQ/128);   // (16, 8)
    k_mm<0><<<gproj, 256, 65536>>>(p_xh, p_wqh, p_q, SEQ, DM, DM, DM, nullptr);
    k_mm<0><<<gproj, 256, 65536>>>(p_xh, p_wkh, p_k, SEQ, DM, DM, DM, nullptr);
    k_mm<0><<<gproj, 256, 65536>>>(p_xh, p_wvh, p_v, SEQ, DM, DM, DM, nullptr);

    k_rope<<<(SEQ*DM/2)/256, 256>>>();
    k_attn3<<<dim3(NH, NBLK, 2), 256, 4*64*AST*4>>>();
    k_attn_norm<<<SEQ*DM/256, 256>>>();

    k_mm<1><<<gproj, 256, 65536>>>(p_attnh, p_woh, p_xres, SEQ, DM, DM, DM, p_x);
    k_ln<<<SEQ, 256>>>(p_xres, ln1g, ln1b, p_xln, p_xlnh);

    k_gate<<<SEQ, 128>>>(gatew);
    k_aux<<<1, 1024>>>(out, out_size);
    k_route<<<SEQ/256, 256>>>();

    // MoE up (128x256 tiles)
    dim3 gup(DFFN/256, CAP/128, NE);   // (32, 8, 4)
    k_mm2<2><<<gup, 256, 98304>>>(p_xlnh, p_w1h, p_h1, CAP, DFFN, DM, DFFN);
    k_mm2<2><<<gup, 256, 98304>>>(p_xlnh, p_w3h, p_h3, CAP, DFFN, DM, DFFN);
    k_silumul<<<(int)(((size_t)NE*CAP*DFFN/2)/256), 256>>>();

    // MoE down scatter (128x256 tiles)
    dim3 gdn(DM/256, CAP/128, NE);     // (8, 8, 4)
    k_mm2<3><<<gdn, 256, 98304>>>(p_h1, p_w2h, nullptr, CAP, DM, DFFN, DM);

    k_lnln<<<SEQ, 256>>>(ln2g, ln2b, fing, finb);

    // head (128x256 tiles)
    dim3 ghead((VOCAB + 255)/256, SEQ/128);  // (197, 8)
    k_mm2<0><<<ghead, 256, 98304>>>(p_xfinh, p_hwh, out, SEQ, VOCAB, DM, VOCAB);
}

// round 15
// speedup vs baseline: 1.5312x; 1.5312x over previous
#include <cuda_runtime.h>
#include <cuda_fp16.h>
#include <math.h>
#include <stdint.h>

#define SEQ   1024
#define DM    2048
#define NH    32
#define HD    64
#define NBLK  16
#define DFFN  8192
#define NE    4
#define CAP   1024
#define VOCAB 50257

// ---------------- scratch (device globals; no allocation) ----------------
static __device__ float  g_x   [SEQ*DM];
static __device__ __half g_xh  [SEQ*DM];
static __device__ float  g_q   [SEQ*DM];
static __device__ float  g_k   [SEQ*DM];
static __device__ float  g_v   [SEQ*DM];
static __device__ float  g_attnf[SEQ*DM];
static __device__ float  g_L   [SEQ*NH];
static __device__ __half g_attnh[SEQ*DM];
static __device__ float  g_xres[SEQ*DM];
static __device__ float  g_xln [SEQ*DM];
static __device__ __half g_xlnh[SEQ*DM];
static __device__ __half g_xfinh[SEQ*DM];
static __device__ float  g_moe [SEQ*DM];
static __device__ float  g_glog[SEQ*NE];
static __device__ int    g_cnt [NE];
static __device__ int    g_idx [NE*CAP];
static __device__ float  g_wt  [NE*CAP];
static __device__ __half g_h1  [(size_t)NE*CAP*DFFN];
static __device__ __half g_h3  [(size_t)NE*CAP*DFFN];
// fp16 weight copies
static __device__ __half g_wqh [DM*DM];
static __device__ __half g_wkh [DM*DM];
static __device__ __half g_wvh [DM*DM];
static __device__ __half g_woh [DM*DM];
static __device__ __half g_w1h [(size_t)NE*DFFN*DM];
static __device__ __half g_w2h [(size_t)NE*DM*DFFN];
static __device__ __half g_w3h [(size_t)NE*DFFN*DM];
static __device__ __half g_hwh [(size_t)VOCAB*DM];

// ---------------- helpers ----------------
__device__ __forceinline__ void ldsm4(uint32_t r[4], uint32_t addr){
    asm volatile("ldmatrix.sync.aligned.m8n8.x4.shared.b16 {%0,%1,%2,%3}, [%4];"
        : "=r"(r[0]), "=r"(r[1]), "=r"(r[2]), "=r"(r[3]) : "r"(addr));
}
__device__ __forceinline__ void mma_fp16(float c[4], const uint32_t a[4], const uint32_t b[2]){
    asm volatile("mma.sync.aligned.m16n8k16.row.col.f32.f16.f16.f32 "
        "{%0,%1,%2,%3},{%4,%5,%6,%7},{%8,%9},{%0,%1,%2,%3};"
        : "+f"(c[0]), "+f"(c[1]), "+f"(c[2]), "+f"(c[3])
        : "r"(a[0]), "r"(a[1]), "r"(a[2]), "r"(a[3]), "r"(b[0]), "r"(b[1]));
}
__device__ __forceinline__ void cpa16(__half* dst, const __half* src, int bytes){
    uint32_t d = (uint32_t)__cvta_generic_to_shared(dst);
    asm volatile("cp.async.cg.shared.global [%0], [%1], 16, %2;" :: "r"(d), "l"(src), "r"(bytes));
}
__device__ __forceinline__ void cpa_commit(){ asm volatile("cp.async.commit_group;"); }
__device__ __forceinline__ void cpa_wait0(){ asm volatile("cp.async.wait_group 0;"); }

// ---------------- fp32 -> fp16 conversion, MLP=8, block-contiguous ----------------
// chunk = 16B of fp16 output (8 elems). Block owns 1024 consecutive chunks.
__global__ void k_f2h(const float* __restrict__ s, __half* __restrict__ d, int n8)
{
    int base = blockIdx.x * 1024 + threadIdx.x;
    const float4* s4 = (const float4*)s;
    uint4* d4 = (uint4*)d;
    float4 a[4][2];
    #pragma unroll
    for (int u = 0; u < 4; u++) {
        int i = base + u*256;
        if (i < n8) {
            a[u][0] = __ldcs(s4 + 2*(size_t)i);
            a[u][1] = __ldcs(s4 + 2*(size_t)i + 1);
        }
    }
    #pragma unroll
    for (int u = 0; u < 4; u++) {
        int i = base + u*256;
        if (i < n8) {
            __half2 h0 = __floats2half2_rn(a[u][0].x, a[u][0].y);
            __half2 h1 = __floats2half2_rn(a[u][0].z, a[u][0].w);
            __half2 h2 = __floats2half2_rn(a[u][1].x, a[u][1].y);
            __half2 h3 = __floats2half2_rn(a[u][1].z, a[u][1].w);
            uint4 o;
            o.x = *(uint32_t*)&h0; o.y = *(uint32_t*)&h1;
            o.z = *(uint32_t*)&h2; o.w = *(uint32_t*)&h3;
            __stcs(d4 + i, o);
        }
    }
}

// ---------------- FP16 GEMM 128x128, 2-stage cp.async (R12-proven) ----------------
template<int GATHER, int SCATTER, int RESID>
__global__ void __launch_bounds__(256) k_mm(
    const __half* __restrict__ A, const __half* __restrict__ Bw,
    void* __restrict__ Cv, int M, int N, int K, int ldc,
    const float* __restrict__ resid)
{
    extern __shared__ __half sm[];
    const int tid = threadIdx.x;
    const int mb = blockIdx.y * 128;
    const int nb = blockIdx.x * 128;
    int cnt = M;
    const int* ridx = nullptr;
    const float* wts = nullptr;
    float* Cf = (float*)Cv;
    __half* Ch = (__half*)Cv;
    if (GATHER || SCATTER) {
        int e = blockIdx.z;
        cnt = g_cnt[e];
        if (mb >= cnt) return;
        ridx = g_idx + e*CAP;
        wts  = g_wt  + e*CAP;
        Bw += (size_t)e * N * K;
        if (GATHER)  Ch += (size_t)e * CAP * N;
        if (SCATTER) A  += (size_t)e * CAP * K;
    }

    const __half* apt[4]; const __half* bpt[4]; int bvalid[4]; int trow[4]; int tseg[4];
    #pragma unroll
    for (int i = 0; i < 4; i++) {
        int task = tid + 256*i;
        int row = task >> 3, seg = task & 7;
        trow[i] = row; tseg[i] = seg;
        int am = mb + row;
        int arow;
        if (GATHER)       arow = (am < cnt) ? ridx[am] : 0;
        else if (SCATTER) arow = (am < cnt) ? am : 0;
        else              arow = am;
        apt[i] = A + (size_t)arow * K + seg*8;
        int bn = nb + row;
        bvalid[i] = (bn < N) ? 16 : 0;
        bpt[i] = Bw + (size_t)((bn < N) ? bn : (N-1)) * K + seg*8;
    }

    auto load_tile = [&](int kt, int buf){
        int k0 = kt * 64;
        __half* base = sm + buf * 16384;
        #pragma unroll
        for (int i = 0; i < 4; i++) {
            int row = trow[i], seg = tseg[i];
            int off = row*64 + ((seg ^ (row & 7)) << 3);
            cpa16(base + off,        apt[i] + k0, 16);
            cpa16(base + 8192 + off, bpt[i] + k0, bvalid[i]);
        }
        cpa_commit();
    };

    const int warp = tid >> 5, lane = tid & 31;
    const int gid = lane >> 2, tig = lane & 3;
    const int lrow = lane & 15, lch = lane >> 4;
    const int wm = (warp & 1) * 64;
    const int wn = (warp >> 1) * 32;
    float acc[4][4][4];
    #pragma unroll
    for (int a = 0; a < 4; a++)
    #pragma unroll
    for (int b = 0; b < 4; b++)
    #pragma unroll
    for (int c = 0; c < 4; c++) acc[a][b][c] = 0.f;

    const uint32_t smbase = (uint32_t)__cvta_generic_to_shared(sm);
    const int nkt = K / 64;
    load_tile(0, 0);
    int p = 0;
    for (int kt = 0; kt < nkt; kt++) {
        cpa_wait0();
        __syncthreads();
        if (kt + 1 < nkt) load_tile(kt + 1, p ^ 1);
        uint32_t abase = smbase + p * 32768;
        uint32_t bbase = abase + 16384;
        #pragma unroll
        for (int ks = 0; ks < 4; ks++) {
            int c0 = ks * 2;
            uint32_t af[4][4];
            #pragma unroll
            for (int mt = 0; mt < 4; mt++) {
                int row = wm + mt*16 + lrow;
                int ch = (c0 + lch) ^ (row & 7);
                ldsm4(af[mt], abase + (row*64 + ch*8)*2);
            }
            uint32_t bfr[2][4];
            #pragma unroll
            for (int bg = 0; bg < 2; bg++) {
                int row = wn + bg*16 + lrow;
                int ch = (c0 + lch) ^ (row & 7);
                ldsm4(bfr[bg], bbase + (row*64 + ch*8)*2);
            }
            #pragma unroll
            for (int mt = 0; mt < 4; mt++)
            #pragma unroll
            for (int nt = 0; nt < 4; nt++) {
                uint32_t bb[2] = { bfr[nt>>1][nt&1], bfr[nt>>1][(nt&1)+2] };
                mma_fp16(acc[mt][nt], af[mt], bb);
            }
        }
        p ^= 1;
    }

    #pragma unroll
    for (int mt = 0; mt < 4; mt++) {
        #pragma unroll
        for (int nt = 0; nt < 4; nt++) {
            int n = nb + wn + nt*8 + tig*2;
            #pragma unroll
            for (int half = 0; half < 2; half++) {
                int m = mb + wm + mt*16 + gid + half*8;
                float v0 = acc[mt][nt][half*2 + 0];
                float v1 = acc[mt][nt][half*2 + 1];
                if (GATHER) {
                    if (m < cnt) {
                        __half2 hv = __floats2half2_rn(v0, v1);
                        *(__half2*)&Ch[(size_t)m*N + n] = hv;
                    }
                } else if (SCATTER) {
                    if (m < cnt) {
                        int tok = ridx[m]; float w = wts[m];
                        atomicAdd(&g_moe[(size_t)tok*DM + n],     w * v0);
                        atomicAdd(&g_moe[(size_t)tok*DM + n + 1], w * v1);
                    }
                } else {
                    if (n < N) {
                        float r0 = RESID ? resid[(size_t)m*ldc + n] : 0.f;
                        Cf[(size_t)m*ldc + n] = v0 + r0;
                    }
                    if (n + 1 < N) {
                        float r1 = RESID ? resid[(size_t)m*ldc + n + 1] : 0.f;
                        Cf[(size_t)m*ldc + n + 1] = v1 + r1;
                    }
                }
            }
        }
    }
}

// ---------------- embedding (fp32 + fp16 copies) ----------------
__global__ void k_embed(const int* __restrict__ tok, const float* __restrict__ emb)
{
    int i = blockIdx.x * blockDim.x + threadIdx.x;
    int t = i >> 11;
    int c = i & 2047;
    float v = emb[(size_t)tok[t]*DM + c];
    g_x[i]  = v;
    g_xh[i] = __float2half_rn(v);
}

// ---------------- h1 = silu(h1) * h3 ----------------
__global__ void k_silumul()
{
    size_t i = (size_t)blockIdx.x * blockDim.x + threadIdx.x;
    __half2 a2 = ((const __half2*)g_h1)[i];
    __half2 b2 = ((const __half2*)g_h3)[i];
    float2 a = __half22float2(a2);
    float2 b = __half22float2(b2);
    float r0 = a.x / (1.f + expf(-a.x)) * b.x;
    float r1 = a.y / (1.f + expf(-a.y)) * b.y;
    ((__half2*)g_h1)[i] = __floats2half2_rn(r0, r1);
}

// ---------------- RoPE ----------------
__global__ void k_rope()
{
    int i = blockIdx.x * blockDim.x + threadIdx.x;
    if (i >= SEQ*DM/2) return;
    int t  = i / (DM/2);
    int cp = i % (DM/2);
    int hp = cp & 31;
    float ex  = -(float)hp * 0.41524101186524409f;
    float inv = exp2f(ex);
    float ang = (float)t * inv;
    float s, c;
    sincosf(ang, &s, &c);
    int base = t*DM + 2*cp;
    float q0 = g_q[base], q1 = g_q[base+1];
    g_q[base]   = q0*c - q1*s;
    g_q[base+1] = q0*s + q1*c;
    float k0 = g_k[base], k1 = g_k[base+1];
    g_k[base]   = k0*c - k1*s;
    g_k[base+1] = k0*s + k1*c;
}

// ---------------- block attention, split over jb parity, atomic accumulate ----------------
#define AST 68
__global__ void __launch_bounds__(256) k_attn3()
{
    extern __shared__ float smf[];
    float* Qs = smf;
    float* Ks = Qs + 64*AST;
    float* Vt = Ks + 64*AST;
    float* Ps = Vt + 64*AST;
    const int h  = blockIdx.x;
    const int ib = (NBLK - 1) - blockIdx.y;
    const int z  = blockIdx.z;
    if (z > ib) return;
    const int tid = threadIdx.x;
    const int rq = (tid >> 4) * 4;
    const int cq = tid & 15;

    {
        int r = tid >> 2, dg = (tid & 3) * 16;
        const float* src = g_q + (size_t)(ib*64 + r)*DM + h*64 + dg;
        float* dst = Qs + r*AST + dg;
        #pragma unroll
        for (int q = 0; q < 4; q++) ((float4*)dst)[q] = ((const float4*)src)[q];
    }

    float acc_o[4][4];
    #pragma unroll
    for (int i = 0; i < 4; i++)
    #pragma unroll
    for (int j = 0; j < 4; j++) acc_o[i][j] = 0.f;
    float lsum[4] = {0.f, 0.f, 0.f, 0.f};

    for (int jb = z; jb <= ib; jb += 2) {
        __syncthreads();
        {
            int r = tid >> 2, dg = (tid & 3) * 16;
            const float* ksrc = g_k + (size_t)(jb*64 + r)*DM + h*64 + dg;
            const float* vsrc = g_v + (size_t)(jb*64 + r)*DM + h*64 + dg;
            float* kd = Ks + r*AST + dg;
            #pragma unroll
            for (int q = 0; q < 4; q++) ((float4*)kd)[q] = ((const float4*)ksrc)[q];
            #pragma unroll
            for (int q = 0; q < 4; q++) {
                float4 v = ((const float4*)vsrc)[q];
                int d0 = dg + 4*q;
                Vt[(d0+0)*AST + r] = v.x;
                Vt[(d0+1)*AST + r] = v.y;
                Vt[(d0+2)*AST + r] = v.z;
                Vt[(d0+3)*AST + r] = v.w;
            }
        }
        __syncthreads();

        float s[4][4];
        #pragma unroll
        for (int i = 0; i < 4; i++)
        #pragma unroll
        for (int j = 0; j < 4; j++) s[i][j] = 0.f;
        for (int d0 = 0; d0 < 64; d0 += 4) {
            float4 q4[4], k4[4];
            #pragma unroll
            for (int i = 0; i < 4; i++) q4[i] = *(const float4*)(Qs + (rq+i)*AST + d0);
            #pragma unroll
            for (int j = 0; j < 4; j++) k4[j] = *(const float4*)(Ks + (cq+16*j)*AST + d0);
            #pragma unroll
            for (int i = 0; i < 4; i++)
            #pragma unroll
            for (int j = 0; j < 4; j++)
                s[i][j] += q4[i].x*k4[j].x + q4[i].y*k4[j].y + q4[i].z*k4[j].z + q4[i].w*k4[j].w;
        }
        #pragma unroll
        for (int i = 0; i < 4; i++)
        #pragma unroll
        for (int j = 0; j < 4; j++) {
            s[i][j] *= 0.125f;
            if (jb == ib && (cq + 16*j) > (rq + i)) s[i][j] = -INFINITY;
        }
        float mx[4];
        #pragma unroll
        for (int i = 0; i < 4; i++) {
            float m = s[i][0];
            #pragma unroll
            for (int j = 1; j < 4; j++) m = fmaxf(m, s[i][j]);
            #pragma unroll
            for (int o = 1; o < 16; o <<= 1) m = fmaxf(m, __shfl_xor_sync(0xffffffffu, m, o));
            mx[i] = m;
        }
        #pragma unroll
        for (int i = 0; i < 4; i++)
        #pragma unroll
        for (int j = 0; j < 4; j++) {
            float pv = expf(s[i][j] - mx[i]);
            lsum[i] += pv;
            Ps[(rq+i)*AST + cq + 16*j] = pv;
        }
        __syncthreads();

        for (int c0 = 0; c0 < 64; c0 += 4) {
            float4 p4[4], v4[4];
            #pragma unroll
            for (int i = 0; i < 4; i++) p4[i] = *(const float4*)(Ps + (rq+i)*AST + c0);
            #pragma unroll
            for (int j = 0; j < 4; j++) v4[j] = *(const float4*)(Vt + (cq+16*j)*AST + c0);
            #pragma unroll
            for (int i = 0; i < 4; i++)
            #pragma unroll
            for (int j = 0; j < 4; j++)
                acc_o[i][j] += p4[i].x*v4[j].x + p4[i].y*v4[j].y + p4[i].z*v4[j].z + p4[i].w*v4[j].w;
        }
    }

    #pragma unroll
    for (int i = 0; i < 4; i++) {
        float l = lsum[i];
        #pragma unroll
        for (int o = 1; o < 16; o <<= 1) l += __shfl_xor_sync(0xffffffffu, l, o);
        if (cq == 0) atomicAdd(&g_L[(ib*64 + rq + i)*NH + h], l);
        #pragma unroll
        for (int j = 0; j < 4; j++)
            atomicAdd(&g_attnf[(size_t)(ib*64 + rq + i)*DM + h*64 + cq + 16*j], acc_o[i][j]);
    }
}

// ---------------- attention normalize ----------------
__global__ void k_attn_norm()
{
    int i = blockIdx.x * blockDim.x + threadIdx.x;
    int t = i >> 11;
    int c = i & 2047;
    int h = c >> 6;
    float l = g_L[t*NH + h];
    g_attnh[i] = __float2half_rn(g_attnf[i] / (l + 1e-6f));
}

// ---------------- layernorm (fp32 + fp16 out) ----------------
__global__ void k_ln(const float* __restrict__ in, const float* __restrict__ g,
                     const float* __restrict__ b, float* __restrict__ out,
                     __half* __restrict__ outh)
{
    __shared__ float red[256];
    const int row = blockIdx.x, tid = threadIdx.x;
    const float* x = in + (size_t)row*DM;
    float s = 0.f;
    for (int c = tid; c < DM; c += 256) s += x[c];
    red[tid] = s; __syncthreads();
    for (int o = 128; o > 0; o >>= 1) { if (tid < o) red[tid] += red[tid+o]; __syncthreads(); }
    float mu = red[0] * (1.f/DM);
    __syncthreads();
    float vs = 0.f;
    for (int c = tid; c < DM; c += 256) { float d = x[c]-mu; vs += d*d; }
    red[tid] = vs; __syncthreads();
    for (int o = 128; o > 0; o >>= 1) { if (tid < o) red[tid] += red[tid+o]; __syncthreads(); }
    float rstd = rsqrtf(red[0]*(1.f/DM) + 1e-5f);
    for (int c = tid; c < DM; c += 256) {
        float v = (x[c]-mu)*rstd*g[c] + b[c];
        out[(size_t)row*DM + c] = v;
        outh[(size_t)row*DM + c] = __float2half_rn(v);
    }
}

// ---------------- fused: v = moe + xln; LN(ln2); LN(fin) -> g_xfinh ----------------
__global__ void k_lnln(const float* __restrict__ g2, const float* __restrict__ b2,
                       const float* __restrict__ gf, const float* __restrict__ bf)
{
    __shared__ float buf[DM];
    __shared__ float red[256];
    const int row = blockIdx.x, tid = threadIdx.x;
    float s = 0.f;
    for (int c = tid; c < DM; c += 256) {
        float v = g_moe[(size_t)row*DM + c] + g_xln[(size_t)row*DM + c];
        buf[c] = v; s += v;
    }
    red[tid] = s; __syncthreads();
    for (int o = 128; o > 0; o >>= 1) { if (tid < o) red[tid] += red[tid+o]; __syncthreads(); }
    float mu = red[0] * (1.f/DM);
    __syncthreads();
    float vs = 0.f;
    for (int c = tid; c < DM; c += 256) { float d = buf[c]-mu; vs += d*d; }
    red[tid] = vs; __syncthreads();
    for (int o = 128; o > 0; o >>= 1) { if (tid < o) red[tid] += red[tid+o]; __syncthreads(); }
    float rstd = rsqrtf(red[0]*(1.f/DM) + 1e-5f);
    __syncthreads();
    for (int c = tid; c < DM; c += 256)
        buf[c] = (buf[c]-mu)*rstd*g2[c] + b2[c];
    __syncthreads();
    s = 0.f;
    for (int c = tid; c < DM; c += 256) s += buf[c];
    red[tid] = s; __syncthreads();
    for (int o = 128; o > 0; o >>= 1) { if (tid < o) red[tid] += red[tid+o]; __syncthreads(); }
    mu = red[0] * (1.f/DM);
    __syncthreads();
    vs = 0.f;
    for (int c = tid; c < DM; c += 256) { float d = buf[c]-mu; vs += d*d; }
    red[tid] = vs; __syncthreads();
    for (int o = 128; o > 0; o >>= 1) { if (tid < o) red[tid] += red[tid+o]; __syncthreads(); }
    rstd = rsqrtf(red[0]*(1.f/DM) + 1e-5f);
    __syncthreads();
    for (int c = tid; c < DM; c += 256)
        g_xfinh[(size_t)row*DM + c] = __float2half_rn((buf[c]-mu)*rstd*gf[c] + bf[c]);
}

// ---------------- gate logits ----------------
__global__ void k_gate(const float* __restrict__ gw)
{
    __shared__ float red[NE*128];
    const int t = blockIdx.x, tid = threadIdx.x;
    float p0=0.f,p1=0.f,p2=0.f,p3=0.f;
    const float* x = g_xln + (size_t)t*DM;
    for (int c = tid; c < DM; c += 128) {
        float xv = x[c];
        p0 += xv * gw[c];
        p1 += xv * gw[DM + c];
        p2 += xv * gw[2*DM + c];
        p3 += xv * gw[3*DM + c];
    }
    red[0*128+tid]=p0; red[1*128+tid]=p1; red[2*128+tid]=p2; red[3*128+tid]=p3;
    __syncthreads();
    for (int o = 64; o > 0; o >>= 1) {
        if (tid < o) {
#pragma unroll
            for (int e = 0; e < NE; e++) red[e*128+tid] += red[e*128+tid+o];
        }
        __syncthreads();
    }
    if (tid < NE) g_glog[t*NE + tid] = red[tid*128];
}

// ---------------- aux ----------------
__global__ void k_aux(float* __restrict__ out, int out_size)
{
    __shared__ float red[1024];
    const int t = threadIdx.x;
    float l0 = g_glog[t*4+0], l1 = g_glog[t*4+1], l2 = g_glog[t*4+2], l3 = g_glog[t*4+3];
    float mu = (l0+l1+l2+l3) * 0.25f;
    float v = ((l0-mu)*(l0-mu) + (l1-mu)*(l1-mu) + (l2-mu)*(l2-mu) + (l3-mu)*(l3-mu)) / 3.f;
    red[t] = v; __syncthreads();
    for (int o = 512; o > 0; o >>= 1) { if (t < o) red[t] += red[t+o]; __syncthreads(); }
    if (t == 0) out[out_size - 1] = red[0] * (1.f/SEQ);
}

// ---------------- zero accumulators + counters ----------------
__global__ void k_zero()
{
    int i = blockIdx.x * blockDim.x + threadIdx.x;
    if (i < SEQ*DM) { g_moe[i] = 0.f; g_attnf[i] = 0.f; }
    if (i < SEQ*NH) g_L[i] = 0.f;
    if (i < NE) g_cnt[i] = 0;
}

// ---------------- routing ----------------
__global__ void k_route()
{
    int t = blockIdx.x * blockDim.x + threadIdx.x;
    if (t >= SEQ) return;
    float l[NE];
#pragma unroll
    for (int e = 0; e < NE; e++) l[e] = g_glog[t*NE + e];
    float m = l[0];
#pragma unroll
    for (int e = 1; e < NE; e++) m = fmaxf(m, l[e]);
    float ex[NE], sum = 0.f;
#pragma unroll
    for (int e = 0; e < NE; e++) { ex[e] = expf(l[e]-m); sum += ex[e]; }
    float p[NE];
#pragma unroll
    for (int e = 0; e < NE; e++) p[e] = ex[e]/sum;
    int i0 = 0;
#pragma unroll
    for (int e = 1; e < NE; e++) if (p[e] > p[i0]) i0 = e;
    int i1 = -1;
#pragma unroll
    for (int e = 0; e < NE; e++) if (e != i0 && (i1 < 0 || p[e] > p[i1])) i1 = e;
    float w0 = p[i0], w1 = p[i1];
    float ws = w0 + w1; w0 /= ws; w1 /= ws;
    int s0 = atomicAdd(&g_cnt[i0], 1);
    g_idx[i0*CAP + s0] = t; g_wt[i0*CAP + s0] = w0;
    int s1 = atomicAdd(&g_cnt[i1], 1);
    g_idx[i1*CAP + s1] = t; g_wt[i1*CAP + s1] = w1;
}

// ---------------- launch ----------------
extern "C" void kernel_launch(void* const* d_in, const int* in_sizes, int n_in,
                              void* d_out, int out_size)
{
    const int*   tokens = (const int*)  d_in[0];
    const float* emb    = (const float*)d_in[1];
    const float* wq     = (const float*)d_in[2];
    const float* wk     = (const float*)d_in[3];
    const float* wv     = (const float*)d_in[4];
    const float* wo     = (const float*)d_in[5];
    const float* ln1g   = (const float*)d_in[6];
    const float* ln1b   = (const float*)d_in[7];
    const float* gatew  = (const float*)d_in[8];
    const float* w1     = (const float*)d_in[9];
    const float* w2     = (const float*)d_in[10];
    const float* w3     = (const float*)d_in[11];
    const float* ln2g   = (const float*)d_in[12];
    const float* ln2b   = (const float*)d_in[13];
    const float* fing   = (const float*)d_in[14];
    const float* finb   = (const float*)d_in[15];
    const float* headw  = (const float*)d_in[16];
    float* out = (float*)d_out;

    float *p_x, *p_q, *p_k, *p_v, *p_xres, *p_xln;
    __half *p_xh, *p_attnh, *p_xlnh, *p_xfinh, *p_h1, *p_h3;
    __half *p_wqh, *p_wkh, *p_wvh, *p_woh, *p_w1h, *p_w2h, *p_w3h, *p_hwh;
    cudaGetSymbolAddress((void**)&p_x,     g_x);
    cudaGetSymbolAddress((void**)&p_q,     g_q);
    cudaGetSymbolAddress((void**)&p_k,     g_k);
    cudaGetSymbolAddress((void**)&p_v,     g_v);
    cudaGetSymbolAddress((void**)&p_xres,  g_xres);
    cudaGetSymbolAddress((void**)&p_xln,   g_xln);
    cudaGetSymbolAddress((void**)&p_xh,    g_xh);
    cudaGetSymbolAddress((void**)&p_attnh, g_attnh);
    cudaGetSymbolAddress((void**)&p_xlnh,  g_xlnh);
    cudaGetSymbolAddress((void**)&p_xfinh, g_xfinh);
    cudaGetSymbolAddress((void**)&p_h1,    g_h1);
    cudaGetSymbolAddress((void**)&p_h3,    g_h3);
    cudaGetSymbolAddress((void**)&p_wqh,   g_wqh);
    cudaGetSymbolAddress((void**)&p_wkh,   g_wkh);
    cudaGetSymbolAddress((void**)&p_wvh,   g_wvh);
    cudaGetSymbolAddress((void**)&p_woh,   g_woh);
    cudaGetSymbolAddress((void**)&p_w1h,   g_w1h);
    cudaGetSymbolAddress((void**)&p_w2h,   g_w2h);
    cudaGetSymbolAddress((void**)&p_w3h,   g_w3h);
    cudaGetSymbolAddress((void**)&p_hwh,   g_hwh);

    static int attr_done = 0;
    if (!attr_done) {
        cudaFuncSetAttribute(k_mm<0,0,0>, cudaFuncAttributeMaxDynamicSharedMemorySize, 65536);
        cudaFuncSetAttribute(k_mm<0,0,1>, cudaFuncAttributeMaxDynamicSharedMemorySize, 65536);
        cudaFuncSetAttribute(k_mm<1,0,0>, cudaFuncAttributeMaxDynamicSharedMemorySize, 65536);
        cudaFuncSetAttribute(k_mm<0,1,0>, cudaFuncAttributeMaxDynamicSharedMemorySize, 65536);
        cudaFuncSetAttribute(k_attn3,     cudaFuncAttributeMaxDynamicSharedMemorySize, 4*64*AST*4);
        attr_done = 1;
    }

    k_zero<<<SEQ*DM/256, 256>>>();

    // ---- weight conversions (fp32 -> fp16), MLP=8 blocked ----
    {
        int n8 = DM*DM/8;
        int g8 = (n8 + 1023) / 1024;
        k_f2h<<<g8, 256>>>(wq, p_wqh, n8);
        k_f2h<<<g8, 256>>>(wk, p_wkh, n8);
        k_f2h<<<g8, 256>>>(wv, p_wvh, n8);
        k_f2h<<<g8, 256>>>(wo, p_woh, n8);
        int nf = (int)((size_t)NE*DFFN*DM/8);
        int gf = (nf + 1023) / 1024;
        k_f2h<<<gf, 256>>>(w1, p_w1h, nf);
        k_f2h<<<gf, 256>>>(w2, p_w2h, nf);
        k_f2h<<<gf, 256>>>(w3, p_w3h, nf);
        int nh = (int)((size_t)VOCAB*DM/8);
        k_f2h<<<(nh + 1023)/1024, 256>>>(headw, p_hwh, nh);
    }

    k_embed<<<SEQ*DM/256, 256>>>(tokens, emb);

    dim3 gproj(DM/128, SEQ/128);   // (16, 8)
    k_mm<0,0,0><<<gproj, 256, 65536>>>(p_xh, p_wqh, p_q, SEQ, DM, DM, DM, nullptr);
    k_mm<0,0,0><<<gproj, 256, 65536>>>(p_xh, p_wkh, p_k, SEQ, DM, DM, DM, nullptr);
    k_mm<0,0,0><<<gproj, 256, 65536>>>(p_xh, p_wvh, p_v, SEQ, DM, DM, DM, nullptr);

    k_rope<<<(SEQ*DM/2)/256, 256>>>();
    k_attn3<<<dim3(NH, NBLK, 2), 256, 4*64*AST*4>>>();
    k_attn_norm<<<SEQ*DM/256, 256>>>();

    k_mm<0,0,1><<<gproj, 256, 65536>>>(p_attnh, p_woh, p_xres, SEQ, DM, DM, DM, p_x);
    k_ln<<<SEQ, 256>>>(p_xres, ln1g, ln1b, p_xln, p_xlnh);

    k_gate<<<SEQ, 128>>>(gatew);
    k_aux<<<1, 1024>>>(out, out_size);
    k_route<<<SEQ/256, 256>>>();

    dim3 gup(DFFN/128, CAP/128, NE);   // (64, 8, 4)
    k_mm<1,0,0><<<gup, 256, 65536>>>(p_xlnh, p_w1h, p_h1, CAP, DFFN, DM, DFFN, nullptr);
    k_mm<1,0,0><<<gup, 256, 65536>>>(p_xlnh, p_w3h, p_h3, CAP, DFFN, DM, DFFN, nullptr);
    k_silumul<<<(int)(((size_t)NE*CAP*DFFN/2)/256), 256>>>();

    dim3 gdn(DM/128, CAP/128, NE);     // (16, 8, 4)
    k_mm<0,1,0><<<gdn, 256, 65536>>>(p_h1, p_w2h, nullptr, CAP, DM, DFFN, DM, nullptr);

    k_lnln<<<SEQ, 256>>>(ln2g, ln2b, fing, finb);

    dim3 ghead((VOCAB + 127)/128, SEQ/128);  // (393, 8)
    k_mm<0,0,0><<<ghead, 256, 65536>>>(p_xfinh, p_hwh, out, SEQ, VOCAB, DM, VOCAB, nullptr);
}